// round 12
// baseline (speedup 1.0000x reference)
#include <cuda_runtime.h>
#include <math.h>

#define TEMP_INV (1.0f/0.07f)
#define NT 256
#define DEPTH 8                    // cp.async pipeline depth (chunks in flight)

// ---------------- device globals (no cudaMalloc allowed) -------------------
__device__ float g_nll[4096];      // per-valid-slot nll
__device__ int   g_vlist[4096];    // compacted valid row indices
__device__ int   g_vlbl[4096];     // label per valid slot
__device__ int   g_nvalid;         // number of valid rows (set each replay)
__device__ float g_sum[512];       // per-anchor sum exp(neg sims): line@0, quat@256
__device__ float g_pos[512];       // per-anchor pos_sim (scaled by 1/TEMP)
__device__ float g_la[256*768];    // normalized line anchors
__device__ float g_qa[256*768];    // normalized quat anchors
__device__ float g_ln[256*768];    // normalized line negatives
__device__ float g_qn[256*768];    // normalized quat negatives
__device__ float g_sonnet;
__device__ int   g_lbl64;
__device__ int   g_done;           // zero at load; reset by last block each replay

// ---------------- warp helpers ---------------------------------------------
__device__ __forceinline__ float wsum(float v) {
    #pragma unroll
    for (int o = 16; o > 0; o >>= 1) v += __shfl_xor_sync(0xffffffffu, v, o);
    return v;
}

// ---------------------------------------------------------------------------
// k_pre block 0: dtype detect -> compact valid rows -> zero accumulators.
// blocks 1..: normalize contrastive rows; anchors get pos_sim precomputed.
// ---------------------------------------------------------------------------
__global__ void k_pre(const long long* __restrict__ labels, int n_labels,
                      const float* __restrict__ la, const float* __restrict__ lp,
                      const float* __restrict__ ln,
                      const float* __restrict__ qa, const float* __restrict__ qp,
                      const float* __restrict__ qn,
                      int Pl, int Pq, int Nl, int Nq) {
    int tid = threadIdx.x;
    if (blockIdx.x == 0) {
        __shared__ int bad;
        if (tid == 0) { bad = 0; g_done = 0; g_nvalid = 0; }
        for (int i = tid; i < 512; i += NT) g_sum[i] = 0.f;
        __syncthreads();
        // dtype detect: int64 layout => high word is sign-extension of low.
        int npairs = n_labels >> 1;
        for (int i = tid; i < npairs; i += NT) {
            long long v = labels[i];
            int lo = (int)(v & 0xffffffffLL);
            int hi = (int)(v >> 32);
            bool ok = (hi == 0 && lo >= 0) || (hi == -1 && lo < 0);
            if (!ok) bad = 1;
        }
        __syncthreads();
        int is64 = bad ? 0 : 1;
        if (tid == 0) g_lbl64 = is64;
        __syncthreads();
        // compact valid rows (order irrelevant; sum is commutative)
        for (int i = tid; i < n_labels; i += NT) {
            int lbl = is64 ? (int)labels[i] : ((const int*)labels)[i];
            if (lbl >= 0) {
                int slot = atomicAdd(&g_nvalid, 1);
                g_vlist[slot] = i;
                g_vlbl[slot]  = lbl;
            }
        }
        return;
    }
    int w = ((blockIdx.x - 1) * NT + tid) >> 5;   // global warp = row id
    int lane = tid & 31;
    int total = Pl + Pq + Nl + Nq;
    if (w >= total) return;

    const float4* src; const float4* pos = 0; float4* dst; int slot = -1;
    if (w < Pl) {
        src = (const float4*)la + (size_t)w * 192;
        pos = (const float4*)lp + (size_t)w * 192;
        dst = (float4*)g_la + (size_t)w * 192; slot = w;
    } else if (w < Pl + Pq) {
        int r = w - Pl;
        src = (const float4*)qa + (size_t)r * 192;
        pos = (const float4*)qp + (size_t)r * 192;
        dst = (float4*)g_qa + (size_t)r * 192; slot = 256 + r;
    } else if (w < Pl + Pq + Nl) {
        int r = w - Pl - Pq;
        src = (const float4*)ln + (size_t)r * 192;
        dst = (float4*)g_ln + (size_t)r * 192;
    } else {
        int r = w - Pl - Pq - Nl;
        src = (const float4*)qn + (size_t)r * 192;
        dst = (float4*)g_qn + (size_t)r * 192;
    }

    float4 v[6];
    float ssq = 0.f;
    #pragma unroll
    for (int i = 0; i < 6; i++) {
        v[i] = src[lane + 32 * i];
        ssq += v[i].x*v[i].x + v[i].y*v[i].y + v[i].z*v[i].z + v[i].w*v[i].w;
    }
    ssq = wsum(ssq);
    float inv = 1.f / fmaxf(sqrtf(ssq), 1e-12f);
    #pragma unroll
    for (int i = 0; i < 6; i++) {
        v[i].x *= inv; v[i].y *= inv; v[i].z *= inv; v[i].w *= inv;
        dst[lane + 32 * i] = v[i];
    }
    if (pos) {   // anchor row: pos_sim = (â · p̂)/TEMP
        float dd = 0.f, pp = 0.f;
        #pragma unroll
        for (int i = 0; i < 6; i++) {
            float4 pv = pos[lane + 32 * i];
            dd += v[i].x*pv.x + v[i].y*pv.y + v[i].z*pv.z + v[i].w*pv.w;
            pp += pv.x*pv.x + pv.y*pv.y + pv.z*pv.z + pv.w*pv.w;
        }
        dd = wsum(dd); pp = wsum(pp);
        if (lane == 0)
            g_pos[slot] = dd / fmaxf(sqrtf(pp), 1e-12f) * TEMP_INV;
    }
}

// ---------------------------------------------------------------------------
// InfoNCE tile block: 8 anchors x 32 negatives (verified since R5).
// shm use: a_s 8*768 floats [0,6144), n_s 32*17 float4 [6144,8320).
// ---------------------------------------------------------------------------
__device__ void tile_block(const float* __restrict__ ganch,
                           const float* __restrict__ gneg,
                           int P, int N, int aBase, int nBase, int slotBase,
                           float* shm) {
    float4* a_s4 = (float4*)shm;             // 8*192 float4
    float4* n_s4 = (float4*)(shm + 6144);    // 32*17 float4 per chunk
    int tid = threadIdx.x, w = tid >> 5, lane = tid & 31;

    const float4* ga4 = (const float4*)ganch;
    for (int idx = tid; idx < 8 * 192; idx += NT) {
        int ar = idx / 192;
        int a = aBase + ar; if (a >= P) a = P - 1;
        a_s4[idx] = ga4[(size_t)a * 192 + (idx - ar * 192)];
    }

    const float4* gn4 = (const float4*)gneg;
    float d = 0.f;
    for (int k0 = 0; k0 < 192; k0 += 16) {
        __syncthreads();
        for (int idx = tid; idx < 512; idx += NT) {
            int rrow = idx >> 4, c = idx & 15;
            int gr = nBase + rrow; if (gr >= N) gr = N - 1;
            n_s4[rrow * 17 + c] = gn4[(size_t)gr * 192 + k0 + c];
        }
        __syncthreads();
        #pragma unroll
        for (int kk = 0; kk < 16; kk++) {
            float4 av = a_s4[w * 192 + k0 + kk];   // warp-uniform broadcast
            float4 nv = n_s4[lane * 17 + kk];      // conflict-free (pitch 17)
            d += av.x * nv.x; d += av.y * nv.y;
            d += av.z * nv.z; d += av.w * nv.w;
        }
    }
    int aIdx = aBase + w, jIdx = nBase + lane;
    float e = (aIdx < P && jIdx < N) ? __expf(d * TEMP_INV) : 0.f;
    e = wsum(e);
    if (lane == 0 && aIdx < P) atomicAdd(&g_sum[slotBase + aIdx], e);
}

// ---------------------------------------------------------------------------
// MLM full row via cp.async ring: DEPTH chunks of 256 float4 (4KB) in flight
// per block, register-free loads. Each thread copies and consumes ONLY its
// own ring slot -> per-thread cp.async group semantics, no barriers in the
// main loop. Ring occupies shm[0..8191]; warp partials at shm[8192..8199].
// ---------------------------------------------------------------------------
__device__ void mlm_row(const float* __restrict__ logits,
                        int V, int r, int lbl, int slot, float* shm) {
    int tid = threadIdx.x;
    const float* row = logits + (size_t)r * V;
    int h = (int)(((16u - ((unsigned)(size_t)row & 15u)) & 15u) >> 2);  // head floats
    if (h > V) h = V;
    int nb = (V - h) >> 2;           // aligned float4 count
    int tail = V - h - (nb << 2);

    float s0 = 0.f, s1 = 0.f, s2 = 0.f, s3 = 0.f;
    if (tid < h)    s0 += __expf(row[tid]);
    if (tid < tail) s1 += __expf(row[h + (nb << 2) + tid]);

    const float4* rb = (const float4*)(row + h);
    int nfull = nb >> 8;             // full 256-float4 chunks

    float4* ring = (float4*)shm;
    unsigned sbase = (unsigned)__cvta_generic_to_shared(ring + tid);

    // prologue: fill pipeline, one commit-group per chunk (uniform count)
    #pragma unroll
    for (int d2 = 0; d2 < DEPTH; d2++) {
        if (d2 < nfull) {
            const float4* src = rb + (d2 << 8) + tid;
            unsigned dst = sbase + d2 * 4096u;
            asm volatile("cp.async.cg.shared.global [%0], [%1], 16;"
                         :: "r"(dst), "l"(src) : "memory");
        }
        asm volatile("cp.async.commit_group;" ::: "memory");
    }
    // main loop: wait chunk c, consume own slot, refill chunk c+DEPTH
    for (int c = 0; c < nfull; c++) {
        asm volatile("cp.async.wait_group %0;" :: "n"(DEPTH - 1) : "memory");
        float4 v = ring[((c & (DEPTH - 1)) << 8) + tid];
        s0 += __expf(v.x); s1 += __expf(v.y); s2 += __expf(v.z); s3 += __expf(v.w);
        int nxt = c + DEPTH;
        if (nxt < nfull) {
            const float4* src = rb + (nxt << 8) + tid;
            unsigned dst = sbase + (unsigned)(nxt & (DEPTH - 1)) * 4096u;
            asm volatile("cp.async.cg.shared.global [%0], [%1], 16;"
                         :: "r"(dst), "l"(src) : "memory");
        }
        asm volatile("cp.async.commit_group;" ::: "memory");
    }
    asm volatile("cp.async.wait_group 0;" ::: "memory");

    // remainder float4s (beyond full chunks)
    for (int i = (nfull << 8) + tid; i < nb; i += NT) {
        float4 v = __ldg(rb + i);
        s0 += __expf(v.x); s1 += __expf(v.y); s2 += __expf(v.z); s3 += __expf(v.w);
    }

    float s = (s0 + s1) + (s2 + s3);
    s = wsum(s);
    if ((tid & 31) == 0) shm[8192 + (tid >> 5)] = s;   // outside ring region
    __syncthreads();
    if (tid < 32) {
        float t = (tid < (NT >> 5)) ? shm[8192 + tid] : 0.f;
        t = wsum(t);
        if (tid == 0) g_nll[slot] = logf(t) - __ldg(&row[lbl]);
    }
}

// ---------------------------------------------------------------------------
// Sonnet: single block, un-staged (L1-hot after norm pass); buffers aliased
// into shm.
// ---------------------------------------------------------------------------
__device__ void sonnet_block(const float* __restrict__ E, int B, int D, float* shm) {
    int tid = threadIdx.x, w = tid >> 5, lane = tid & 31;
    float* norminv = shm;           // 32
    float* simbuf  = shm + 32;      // B*B <= 1024
    float* rowloss = shm + 1056;    // 32

    for (int r = w; r < B; r += (NT >> 5)) {
        const float* rowp = E + (size_t)r * D;
        float ssq = 0.f;
        for (int i = lane; i < D; i += 32) { float v = __ldg(&rowp[i]); ssq += v * v; }
        ssq = wsum(ssq);
        if (lane == 0) norminv[r] = 1.f / fmaxf(sqrtf(ssq), 1e-12f);
    }
    __syncthreads();
    for (int t = tid; t < B * B; t += NT) {
        int i = t / B, j = t % B;
        const float* ri = E + (size_t)i * D;
        const float* rj = E + (size_t)j * D;
        float d = 0.f;
        #pragma unroll 8
        for (int k = 0; k < D; k++) d += __ldg(&ri[k]) * __ldg(&rj[k]);
        simbuf[i * B + j] = d * norminv[i] * norminv[j] * TEMP_INV;
    }
    __syncthreads();
    if (tid < B) {
        float m = -3e38f;
        for (int j = 0; j < B; j++) m = fmaxf(m, simbuf[tid * B + j]);
        float se = 0.f;
        for (int j = 0; j < B; j++) se += __expf(simbuf[tid * B + j] - m);
        rowloss[tid] = m + logf(se) - simbuf[tid * B + tid];
    }
    __syncthreads();
    if (tid == 0) {
        float s = 0.f;
        for (int i = 0; i < B; i++) s += rowloss[i];
        g_sonnet = s / (float)B;
    }
}

// ---------------------------------------------------------------------------
// Fused kernel: [line tiles | quat tiles | sonnet | compacted MLM slots].
// shm = 8352 floats (33.4KB): tiles use [0,8320); MLM ring [0,8192) +
// reduce [8192,8200); sonnet aliases [0,1088).
// ---------------------------------------------------------------------------
__global__ void __launch_bounds__(NT)
k_fused(const float* __restrict__ mlm_logits,
        const float* __restrict__ sonnet,
        int rows, int V,
        int Pl, int Nl, int ATl, int NTl,
        int Pq, int Nq, int ATq, int NTq,
        int Bs, int D, int totalBlocks,
        float* __restrict__ out) {
    __shared__ float shm[8352];
    __shared__ int isLast;
    int b = blockIdx.x;
    int tid = threadIdx.x;
    int TLl = ATl * NTl, TLq = ATq * NTq;
    int nv = g_nvalid;

    if (b < TLl) {
        tile_block(g_la, g_ln, Pl, Nl, (b / NTl) * 8, (b % NTl) * 32, 0, shm);
    } else if (b < TLl + TLq) {
        int bb = b - TLl;
        tile_block(g_qa, g_qn, Pq, Nq, (bb / NTq) * 8, (bb % NTq) * 32, 256, shm);
    } else if (b == TLl + TLq) {
        sonnet_block(sonnet, Bs, D, shm);
    } else {
        int slot = b - (TLl + TLq + 1);
        if (slot < nv)
            mlm_row(mlm_logits, V, g_vlist[slot], g_vlbl[slot], slot, shm);
    }

    // ---- completion protocol ----
    __syncthreads();
    __threadfence();
    if (tid == 0) {
        int v = atomicAdd(&g_done, 1);
        isLast = (v == totalBlocks - 1);
    }
    __syncthreads();
    if (!isLast) return;
    __threadfence();

    float s = 0.f, l = 0.f, q = 0.f;
    for (int i = tid; i < nv; i += NT) s += g_nll[i];
    for (int p = tid; p < Pl; p += NT) {
        float ps = g_pos[p];
        l += logf(g_sum[p] + __expf(ps)) - ps;
    }
    for (int p = tid; p < Pq; p += NT) {
        float ps = g_pos[256 + p];
        q += logf(g_sum[256 + p] + __expf(ps)) - ps;
    }
    __syncthreads();  // all reads done before re-zeroing
    for (int i = tid; i < 512; i += NT) g_sum[i] = 0.f;

    shm[tid] = s; shm[256 + tid] = l; shm[512 + tid] = q;
    __syncthreads();
    for (int off = NT >> 1; off > 0; off >>= 1) {
        if (tid < off) {
            shm[tid]       += shm[tid + off];
            shm[256 + tid] += shm[256 + tid + off];
            shm[512 + tid] += shm[512 + tid + off];
        }
        __syncthreads();
    }
    if (tid == 0) {
        float mlm = shm[0] / fmaxf((float)nv, 1.f);
        out[0] = 0.5f * mlm
               + 0.2f * shm[256] / (float)Pl
               + 0.2f * shm[512] / (float)Pq
               + 0.1f * g_sonnet;
        g_done = 0;   // reset for next graph replay
    }
}

// ---------------------------------------------------------------------------
extern "C" void kernel_launch(void* const* d_in, const int* in_sizes, int n_in,
                              void* d_out, int out_size) {
    const float* mlm_logits = (const float*)d_in[0];
    const void*  mlm_labels = d_in[1];
    const float* la = (const float*)d_in[2];
    const float* lp = (const float*)d_in[3];
    const float* ln = (const float*)d_in[4];
    const float* qa = (const float*)d_in[5];
    const float* qp = (const float*)d_in[6];
    const float* qn = (const float*)d_in[7];
    const float* so = (const float*)d_in[8];

    int rows = in_sizes[1];                        // B*S = 4096
    int V = (int)((long long)in_sizes[0] / rows);  // 30522
    const int D = 768;
    int Pl = in_sizes[2] / D, Nl = in_sizes[4] / D;
    int Pq = in_sizes[5] / D, Nq = in_sizes[7] / D;
    int Bs = in_sizes[8] / D;

    int ATl = (Pl + 7) / 8, NTl = (Nl + 31) / 32;
    int ATq = (Pq + 7) / 8, NTq = (Nq + 31) / 32;
    int tiles = ATl * NTl + ATq * NTq;
    int total = tiles + 1 + rows;

    int prepRows = Pl + Pq + Nl + Nq;
    int prepBlocks = 1 + (prepRows * 32 + NT - 1) / NT;

    k_pre<<<prepBlocks, NT>>>((const long long*)mlm_labels, rows,
                              la, lp, ln, qa, qp, qn, Pl, Pq, Nl, Nq);
    k_fused<<<total, NT>>>(mlm_logits, so,
                           rows, V, Pl, Nl, ATl, NTl, Pq, Nq, ATq, NTq,
                           Bs, D, total, (float*)d_out);
}

// round 13
// speedup vs baseline: 1.0902x; 1.0902x over previous
#include <cuda_runtime.h>
#include <math.h>

#define TEMP_INV (1.0f/0.07f)
#define NT 256
#define CHUNK_F4 1024              // 16KB chunks (float4 units)

// ---------------- device globals (no cudaMalloc allowed) -------------------
__device__ float g_nll[4096];      // per-valid-slot nll
__device__ int   g_vlist[4096];    // compacted valid row indices
__device__ int   g_vlbl[4096];     // label per valid slot
__device__ int   g_nvalid;         // number of valid rows (set each replay)
__device__ float g_sum[512];       // per-anchor sum exp(neg sims): line@0, quat@256
__device__ float g_pos[512];       // per-anchor pos_sim (scaled by 1/TEMP)
__device__ float g_la[256*768];    // normalized line anchors
__device__ float g_qa[256*768];    // normalized quat anchors
__device__ float g_ln[256*768];    // normalized line negatives
__device__ float g_qn[256*768];    // normalized quat negatives
__device__ float g_sonnet;
__device__ int   g_lbl64;
__device__ int   g_done;           // zero at load; reset by last block each replay

// ---------------- warp helpers ---------------------------------------------
__device__ __forceinline__ float wsum(float v) {
    #pragma unroll
    for (int o = 16; o > 0; o >>= 1) v += __shfl_xor_sync(0xffffffffu, v, o);
    return v;
}

// ---------------- mbarrier / bulk-TMA helpers -------------------------------
__device__ __forceinline__ void mbar_init(unsigned mbar, unsigned count) {
    asm volatile("mbarrier.init.shared.b64 [%0], %1;" :: "r"(mbar), "r"(count) : "memory");
}
__device__ __forceinline__ void mbar_expect_tx(unsigned mbar, unsigned bytes) {
    asm volatile("mbarrier.arrive.expect_tx.shared.b64 _, [%0], %1;"
                 :: "r"(mbar), "r"(bytes) : "memory");
}
__device__ __forceinline__ void mbar_wait(unsigned mbar, unsigned parity) {
    asm volatile(
        "{\n\t.reg .pred P;\n\t"
        "WAIT_%=:\n\t"
        "mbarrier.try_wait.parity.acquire.cta.shared::cta.b64 P, [%0], %1, 0x989680;\n\t"
        "@!P bra WAIT_%=;\n\t"
        "}" :: "r"(mbar), "r"(parity) : "memory");
}
__device__ __forceinline__ void bulk_ldg(unsigned dst_smem, const void* src,
                                         unsigned bytes, unsigned mbar) {
    asm volatile(
        "cp.async.bulk.shared::cluster.global.mbarrier::complete_tx::bytes "
        "[%0], [%1], %2, [%3];"
        :: "r"(dst_smem), "l"(src), "r"(bytes), "r"(mbar) : "memory");
}

// ---------------------------------------------------------------------------
// k_pre block 0: dtype detect -> compact valid rows -> zero accumulators.
// blocks 1..: normalize contrastive rows; anchors get pos_sim precomputed.
// ---------------------------------------------------------------------------
__global__ void k_pre(const long long* __restrict__ labels, int n_labels,
                      const float* __restrict__ la, const float* __restrict__ lp,
                      const float* __restrict__ ln,
                      const float* __restrict__ qa, const float* __restrict__ qp,
                      const float* __restrict__ qn,
                      int Pl, int Pq, int Nl, int Nq) {
    int tid = threadIdx.x;
    if (blockIdx.x == 0) {
        __shared__ int bad;
        if (tid == 0) { bad = 0; g_done = 0; g_nvalid = 0; }
        for (int i = tid; i < 512; i += NT) g_sum[i] = 0.f;
        __syncthreads();
        // dtype detect: int64 layout => high word is sign-extension of low.
        int npairs = n_labels >> 1;
        for (int i = tid; i < npairs; i += NT) {
            long long v = labels[i];
            int lo = (int)(v & 0xffffffffLL);
            int hi = (int)(v >> 32);
            bool ok = (hi == 0 && lo >= 0) || (hi == -1 && lo < 0);
            if (!ok) bad = 1;
        }
        __syncthreads();
        int is64 = bad ? 0 : 1;
        if (tid == 0) g_lbl64 = is64;
        __syncthreads();
        // compact valid rows (order irrelevant; sum is commutative)
        for (int i = tid; i < n_labels; i += NT) {
            int lbl = is64 ? (int)labels[i] : ((const int*)labels)[i];
            if (lbl >= 0) {
                int slot = atomicAdd(&g_nvalid, 1);
                g_vlist[slot] = i;
                g_vlbl[slot]  = lbl;
            }
        }
        return;
    }
    int w = ((blockIdx.x - 1) * NT + tid) >> 5;   // global warp = row id
    int lane = tid & 31;
    int total = Pl + Pq + Nl + Nq;
    if (w >= total) return;

    const float4* src; const float4* pos = 0; float4* dst; int slot = -1;
    if (w < Pl) {
        src = (const float4*)la + (size_t)w * 192;
        pos = (const float4*)lp + (size_t)w * 192;
        dst = (float4*)g_la + (size_t)w * 192; slot = w;
    } else if (w < Pl + Pq) {
        int r = w - Pl;
        src = (const float4*)qa + (size_t)r * 192;
        pos = (const float4*)qp + (size_t)r * 192;
        dst = (float4*)g_qa + (size_t)r * 192; slot = 256 + r;
    } else if (w < Pl + Pq + Nl) {
        int r = w - Pl - Pq;
        src = (const float4*)ln + (size_t)r * 192;
        dst = (float4*)g_ln + (size_t)r * 192;
    } else {
        int r = w - Pl - Pq - Nl;
        src = (const float4*)qn + (size_t)r * 192;
        dst = (float4*)g_qn + (size_t)r * 192;
    }

    float4 v[6];
    float ssq = 0.f;
    #pragma unroll
    for (int i = 0; i < 6; i++) {
        v[i] = src[lane + 32 * i];
        ssq += v[i].x*v[i].x + v[i].y*v[i].y + v[i].z*v[i].z + v[i].w*v[i].w;
    }
    ssq = wsum(ssq);
    float inv = 1.f / fmaxf(sqrtf(ssq), 1e-12f);
    #pragma unroll
    for (int i = 0; i < 6; i++) {
        v[i].x *= inv; v[i].y *= inv; v[i].z *= inv; v[i].w *= inv;
        dst[lane + 32 * i] = v[i];
    }
    if (pos) {   // anchor row: pos_sim = (â · p̂)/TEMP
        float dd = 0.f, pp = 0.f;
        #pragma unroll
        for (int i = 0; i < 6; i++) {
            float4 pv = pos[lane + 32 * i];
            dd += v[i].x*pv.x + v[i].y*pv.y + v[i].z*pv.z + v[i].w*pv.w;
            pp += pv.x*pv.x + pv.y*pv.y + pv.z*pv.z + pv.w*pv.w;
        }
        dd = wsum(dd); pp = wsum(pp);
        if (lane == 0)
            g_pos[slot] = dd / fmaxf(sqrtf(pp), 1e-12f) * TEMP_INV;
    }
}

// ---------------------------------------------------------------------------
// InfoNCE tile block: 8 anchors x 32 negatives (verified since R5).
// shm use: a_s 8*768 floats [0,6144), n_s 32*17 float4 [6144,8320).
// ---------------------------------------------------------------------------
__device__ void tile_block(const float* __restrict__ ganch,
                           const float* __restrict__ gneg,
                           int P, int N, int aBase, int nBase, int slotBase,
                           float* shm) {
    float4* a_s4 = (float4*)shm;             // 8*192 float4
    float4* n_s4 = (float4*)(shm + 6144);    // 32*17 float4 per chunk
    int tid = threadIdx.x, w = tid >> 5, lane = tid & 31;

    const float4* ga4 = (const float4*)ganch;
    for (int idx = tid; idx < 8 * 192; idx += NT) {
        int ar = idx / 192;
        int a = aBase + ar; if (a >= P) a = P - 1;
        a_s4[idx] = ga4[(size_t)a * 192 + (idx - ar * 192)];
    }

    const float4* gn4 = (const float4*)gneg;
    float d = 0.f;
    for (int k0 = 0; k0 < 192; k0 += 16) {
        __syncthreads();
        for (int idx = tid; idx < 512; idx += NT) {
            int rrow = idx >> 4, c = idx & 15;
            int gr = nBase + rrow; if (gr >= N) gr = N - 1;
            n_s4[rrow * 17 + c] = gn4[(size_t)gr * 192 + k0 + c];
        }
        __syncthreads();
        #pragma unroll
        for (int kk = 0; kk < 16; kk++) {
            float4 av = a_s4[w * 192 + k0 + kk];   // warp-uniform broadcast
            float4 nv = n_s4[lane * 17 + kk];      // conflict-free (pitch 17)
            d += av.x * nv.x; d += av.y * nv.y;
            d += av.z * nv.z; d += av.w * nv.w;
        }
    }
    int aIdx = aBase + w, jIdx = nBase + lane;
    float e = (aIdx < P && jIdx < N) ? __expf(d * TEMP_INV) : 0.f;
    e = wsum(e);
    if (lane == 0 && aIdx < P) atomicAdd(&g_sum[slotBase + aIdx], e);
}

// ---------------------------------------------------------------------------
// MLM full row via bulk-TMA double buffer: 16KB chunks, mbarrier-paced.
// In-flight bytes are guaranteed by construction (not by the register
// allocator). Ring = shm[0,8192); reduce at shm[8192..].
// ---------------------------------------------------------------------------
__device__ void mlm_row(const float* __restrict__ logits,
                        int V, int r, int lbl, int slot, float* shm,
                        unsigned long long* mbar) {
    int tid = threadIdx.x;
    const float* row = logits + (size_t)r * V;
    int h = (int)(((16u - ((unsigned)(size_t)row & 15u)) & 15u) >> 2);  // head floats
    if (h > V) h = V;
    int nb = (V - h) >> 2;           // aligned float4 count
    int tail = V - h - (nb << 2);

    float s0 = 0.f, s1 = 0.f, s2 = 0.f, s3 = 0.f;
    if (tid < h)    s0 += __expf(row[tid]);
    if (tid < tail) s1 += __expf(row[h + (nb << 2) + tid]);

    const float4* rb = (const float4*)(row + h);
    int nchunks = (nb + CHUNK_F4 - 1) / CHUNK_F4;

    unsigned mb0 = (unsigned)__cvta_generic_to_shared(mbar);
    unsigned mb1 = mb0 + 8;
    unsigned ringAddr = (unsigned)__cvta_generic_to_shared(shm);
    float4* ring = (float4*)shm;

    if (tid == 0) { mbar_init(mb0, 1); mbar_init(mb1, 1); }
    __syncthreads();

    // prologue: fill both buffers
    if (tid == 0) {
        {
            unsigned bytes = (unsigned)((nb < CHUNK_F4 ? nb : CHUNK_F4) * 16);
            mbar_expect_tx(mb0, bytes);
            bulk_ldg(ringAddr, rb, bytes, mb0);
        }
        if (nchunks > 1) {
            int cnt = nb - CHUNK_F4; if (cnt > CHUNK_F4) cnt = CHUNK_F4;
            unsigned bytes = (unsigned)(cnt * 16);
            mbar_expect_tx(mb1, bytes);
            bulk_ldg(ringAddr + CHUNK_F4 * 16u, rb + CHUNK_F4, bytes, mb1);
        }
    }

    for (int c = 0; c < nchunks; c++) {
        int buf = c & 1;
        mbar_wait(buf ? mb1 : mb0, (c >> 1) & 1);
        int start = c * CHUNK_F4;
        int cnt = nb - start; if (cnt > CHUNK_F4) cnt = CHUNK_F4;
        const float4* bp = ring + buf * CHUNK_F4;
        for (int i = tid; i < cnt; i += NT) {
            float4 v = bp[i];
            s0 += __expf(v.x); s1 += __expf(v.y); s2 += __expf(v.z); s3 += __expf(v.w);
        }
        __syncthreads();   // all consumed before refill of this buffer
        int nxt = c + 2;
        if (nxt < nchunks && tid == 0) {
            int ncnt = nb - nxt * CHUNK_F4; if (ncnt > CHUNK_F4) ncnt = CHUNK_F4;
            unsigned bytes = (unsigned)(ncnt * 16);
            unsigned mb = buf ? mb1 : mb0;
            mbar_expect_tx(mb, bytes);
            bulk_ldg(ringAddr + (unsigned)buf * (CHUNK_F4 * 16u),
                     rb + nxt * CHUNK_F4, bytes, mb);
        }
    }

    float s = (s0 + s1) + (s2 + s3);
    s = wsum(s);
    if ((tid & 31) == 0) shm[8192 + (tid >> 5)] = s;
    __syncthreads();
    if (tid < 32) {
        float t = (tid < (NT >> 5)) ? shm[8192 + tid] : 0.f;
        t = wsum(t);
        if (tid == 0) g_nll[slot] = logf(t) - __ldg(&row[lbl]);
    }
}

// ---------------------------------------------------------------------------
// Sonnet: single block, un-staged; buffers aliased into shm.
// ---------------------------------------------------------------------------
__device__ void sonnet_block(const float* __restrict__ E, int B, int D, float* shm) {
    int tid = threadIdx.x, w = tid >> 5, lane = tid & 31;
    float* norminv = shm;           // 32
    float* simbuf  = shm + 32;      // B*B <= 1024
    float* rowloss = shm + 1056;    // 32

    for (int r = w; r < B; r += (NT >> 5)) {
        const float* rowp = E + (size_t)r * D;
        float ssq = 0.f;
        for (int i = lane; i < D; i += 32) { float v = __ldg(&rowp[i]); ssq += v * v; }
        ssq = wsum(ssq);
        if (lane == 0) norminv[r] = 1.f / fmaxf(sqrtf(ssq), 1e-12f);
    }
    __syncthreads();
    for (int t = tid; t < B * B; t += NT) {
        int i = t / B, j = t % B;
        const float* ri = E + (size_t)i * D;
        const float* rj = E + (size_t)j * D;
        float d = 0.f;
        #pragma unroll 8
        for (int k = 0; k < D; k++) d += __ldg(&ri[k]) * __ldg(&rj[k]);
        simbuf[i * B + j] = d * norminv[i] * norminv[j] * TEMP_INV;
    }
    __syncthreads();
    if (tid < B) {
        float m = -3e38f;
        for (int j = 0; j < B; j++) m = fmaxf(m, simbuf[tid * B + j]);
        float se = 0.f;
        for (int j = 0; j < B; j++) se += __expf(simbuf[tid * B + j] - m);
        rowloss[tid] = m + logf(se) - simbuf[tid * B + tid];
    }
    __syncthreads();
    if (tid == 0) {
        float s = 0.f;
        for (int i = 0; i < B; i++) s += rowloss[i];
        g_sonnet = s / (float)B;
    }
}

// ---------------------------------------------------------------------------
// Fused kernel: [line tiles | quat tiles | sonnet | compacted MLM slots].
// Dead slots exit BEFORE the completion protocol; expected block count is
// tiles+1+nv, computed on-device.
// ---------------------------------------------------------------------------
__global__ void __launch_bounds__(NT)
k_fused(const float* __restrict__ mlm_logits,
        const float* __restrict__ sonnet,
        int rows, int V,
        int Pl, int Nl, int ATl, int NTl,
        int Pq, int Nq, int ATq, int NTq,
        int Bs, int D,
        float* __restrict__ out) {
    __shared__ __align__(128) float shm[8352];
    __shared__ __align__(8) unsigned long long mbar[2];
    __shared__ int isLast;
    int b = blockIdx.x;
    int tid = threadIdx.x;
    int TLl = ATl * NTl, TLq = ATq * NTq;
    int base = TLl + TLq + 1;
    int nv = g_nvalid;

    if (b < TLl) {
        tile_block(g_la, g_ln, Pl, Nl, (b / NTl) * 8, (b % NTl) * 32, 0, shm);
    } else if (b < TLl + TLq) {
        int bb = b - TLl;
        tile_block(g_qa, g_qn, Pq, Nq, (bb / NTq) * 8, (bb % NTq) * 32, 256, shm);
    } else if (b == TLl + TLq) {
        sonnet_block(sonnet, Bs, D, shm);
    } else {
        int slot = b - base;
        if (slot >= nv) return;   // dead slot: no protocol participation
        mlm_row(mlm_logits, V, g_vlist[slot], g_vlbl[slot], slot, shm, mbar);
    }

    // ---- completion protocol (participants = base + nv blocks) ----
    __syncthreads();
    __threadfence();
    if (tid == 0) {
        int v = atomicAdd(&g_done, 1);
        isLast = (v == base + nv - 1);
    }
    __syncthreads();
    if (!isLast) return;
    __threadfence();

    float s = 0.f, l = 0.f, q = 0.f;
    for (int i = tid; i < nv; i += NT) s += g_nll[i];
    for (int p = tid; p < Pl; p += NT) {
        float ps = g_pos[p];
        l += logf(g_sum[p] + __expf(ps)) - ps;
    }
    for (int p = tid; p < Pq; p += NT) {
        float ps = g_pos[256 + p];
        q += logf(g_sum[256 + p] + __expf(ps)) - ps;
    }
    __syncthreads();  // all reads done before re-zeroing
    for (int i = tid; i < 512; i += NT) g_sum[i] = 0.f;

    shm[tid] = s; shm[256 + tid] = l; shm[512 + tid] = q;
    __syncthreads();
    for (int off = NT >> 1; off > 0; off >>= 1) {
        if (tid < off) {
            shm[tid]       += shm[tid + off];
            shm[256 + tid] += shm[256 + tid + off];
            shm[512 + tid] += shm[512 + tid + off];
        }
        __syncthreads();
    }
    if (tid == 0) {
        float mlm = shm[0] / fmaxf((float)nv, 1.f);
        out[0] = 0.5f * mlm
               + 0.2f * shm[256] / (float)Pl
               + 0.2f * shm[512] / (float)Pq
               + 0.1f * g_sonnet;
        g_done = 0;   // reset for next graph replay
    }
}

// ---------------------------------------------------------------------------
extern "C" void kernel_launch(void* const* d_in, const int* in_sizes, int n_in,
                              void* d_out, int out_size) {
    const float* mlm_logits = (const float*)d_in[0];
    const void*  mlm_labels = d_in[1];
    const float* la = (const float*)d_in[2];
    const float* lp = (const float*)d_in[3];
    const float* ln = (const float*)d_in[4];
    const float* qa = (const float*)d_in[5];
    const float* qp = (const float*)d_in[6];
    const float* qn = (const float*)d_in[7];
    const float* so = (const float*)d_in[8];

    int rows = in_sizes[1];                        // B*S = 4096
    int V = (int)((long long)in_sizes[0] / rows);  // 30522
    const int D = 768;
    int Pl = in_sizes[2] / D, Nl = in_sizes[4] / D;
    int Pq = in_sizes[5] / D, Nq = in_sizes[7] / D;
    int Bs = in_sizes[8] / D;

    int ATl = (Pl + 7) / 8, NTl = (Nl + 31) / 32;
    int ATq = (Pq + 7) / 8, NTq = (Nq + 31) / 32;
    int tiles = ATl * NTl + ATq * NTq;
    int total = tiles + 1 + rows;

    int prepRows = Pl + Pq + Nl + Nq;
    int prepBlocks = 1 + (prepRows * 32 + NT - 1) / NT;

    k_pre<<<prepBlocks, NT>>>((const long long*)mlm_labels, rows,
                              la, lp, ln, qa, qp, qn, Pl, Pq, Nl, Nq);
    k_fused<<<total, NT>>>(mlm_logits, so,
                           rows, V, Pl, Nl, ATl, NTl, Pq, Nq, ATq, NTq,
                           Bs, D, (float*)d_out);
}

// round 14
// speedup vs baseline: 2.7087x; 2.4846x over previous
#include <cuda_runtime.h>
#include <math.h>

#define TEMP_INV (1.0f/0.07f)
#define NT 256

// ---------------- device globals (no cudaMalloc allowed) -------------------
__device__ float g_nll[4096];      // per-valid-slot nll
__device__ int   g_vlist[4096];    // compacted valid row indices
__device__ int   g_vlbl[4096];     // label per valid slot
__device__ int   g_nvalid;         // number of valid rows (set each replay)
__device__ float g_sum[512];       // per-anchor sum exp(neg sims): line@0, quat@256
__device__ float g_pos[512];       // per-anchor pos_sim (scaled by 1/TEMP)
__device__ float g_la[256*768];    // normalized line anchors
__device__ float g_qa[256*768];    // normalized quat anchors
__device__ float g_ln[256*768];    // normalized line negatives
__device__ float g_qn[256*768];    // normalized quat negatives
__device__ float g_sonnet;
__device__ int   g_lbl64;
__device__ int   g_done;           // zero at load; reset by last block each replay

// ---------------- warp helpers ---------------------------------------------
__device__ __forceinline__ float wsum(float v) {
    #pragma unroll
    for (int o = 16; o > 0; o >>= 1) v += __shfl_xor_sync(0xffffffffu, v, o);
    return v;
}

// ---------------------------------------------------------------------------
// k_pre block 0: dtype detect -> compact valid rows -> zero accumulators.
// blocks 1..: normalize contrastive rows; anchors get pos_sim precomputed.
// ---------------------------------------------------------------------------
__global__ void k_pre(const long long* __restrict__ labels, int n_labels,
                      const float* __restrict__ la, const float* __restrict__ lp,
                      const float* __restrict__ ln,
                      const float* __restrict__ qa, const float* __restrict__ qp,
                      const float* __restrict__ qn,
                      int Pl, int Pq, int Nl, int Nq) {
    int tid = threadIdx.x;
    if (blockIdx.x == 0) {
        __shared__ int bad;
        if (tid == 0) { bad = 0; g_done = 0; g_nvalid = 0; }
        for (int i = tid; i < 512; i += NT) g_sum[i] = 0.f;
        __syncthreads();
        // dtype detect: int64 layout => high word is sign-extension of low.
        int npairs = n_labels >> 1;
        for (int i = tid; i < npairs; i += NT) {
            long long v = labels[i];
            int lo = (int)(v & 0xffffffffLL);
            int hi = (int)(v >> 32);
            bool ok = (hi == 0 && lo >= 0) || (hi == -1 && lo < 0);
            if (!ok) bad = 1;
        }
        __syncthreads();
        int is64 = bad ? 0 : 1;
        if (tid == 0) g_lbl64 = is64;
        __syncthreads();
        // compact valid rows (order irrelevant; sum is commutative)
        for (int i = tid; i < n_labels; i += NT) {
            int lbl = is64 ? (int)labels[i] : ((const int*)labels)[i];
            if (lbl >= 0) {
                int slot = atomicAdd(&g_nvalid, 1);
                g_vlist[slot] = i;
                g_vlbl[slot]  = lbl;
            }
        }
        return;
    }
    int w = ((blockIdx.x - 1) * NT + tid) >> 5;   // global warp = row id
    int lane = tid & 31;
    int total = Pl + Pq + Nl + Nq;
    if (w >= total) return;

    const float4* src; const float4* pos = 0; float4* dst; int slot = -1;
    if (w < Pl) {
        src = (const float4*)la + (size_t)w * 192;
        pos = (const float4*)lp + (size_t)w * 192;
        dst = (float4*)g_la + (size_t)w * 192; slot = w;
    } else if (w < Pl + Pq) {
        int r = w - Pl;
        src = (const float4*)qa + (size_t)r * 192;
        pos = (const float4*)qp + (size_t)r * 192;
        dst = (float4*)g_qa + (size_t)r * 192; slot = 256 + r;
    } else if (w < Pl + Pq + Nl) {
        int r = w - Pl - Pq;
        src = (const float4*)ln + (size_t)r * 192;
        dst = (float4*)g_ln + (size_t)r * 192;
    } else {
        int r = w - Pl - Pq - Nl;
        src = (const float4*)qn + (size_t)r * 192;
        dst = (float4*)g_qn + (size_t)r * 192;
    }

    float4 v[6];
    float ssq = 0.f;
    #pragma unroll
    for (int i = 0; i < 6; i++) {
        v[i] = src[lane + 32 * i];
        ssq += v[i].x*v[i].x + v[i].y*v[i].y + v[i].z*v[i].z + v[i].w*v[i].w;
    }
    ssq = wsum(ssq);
    float inv = 1.f / fmaxf(sqrtf(ssq), 1e-12f);
    #pragma unroll
    for (int i = 0; i < 6; i++) {
        v[i].x *= inv; v[i].y *= inv; v[i].z *= inv; v[i].w *= inv;
        dst[lane + 32 * i] = v[i];
    }
    if (pos) {   // anchor row: pos_sim = (â · p̂)/TEMP
        float dd = 0.f, pp = 0.f;
        #pragma unroll
        for (int i = 0; i < 6; i++) {
            float4 pv = pos[lane + 32 * i];
            dd += v[i].x*pv.x + v[i].y*pv.y + v[i].z*pv.z + v[i].w*pv.w;
            pp += pv.x*pv.x + pv.y*pv.y + pv.z*pv.z + pv.w*pv.w;
        }
        dd = wsum(dd); pp = wsum(pp);
        if (lane == 0)
            g_pos[slot] = dd / fmaxf(sqrtf(pp), 1e-12f) * TEMP_INV;
    }
}

// ---------------------------------------------------------------------------
// InfoNCE tile block, k-split version: 8 anchors x 32 negatives per block.
// Lane j owns negative nBase+j for ALL 8 anchors; warp w covers the kk's
// with (kk mod 8 == w) in each staged chunk (disjoint k interleave).
// Per kk per warp: 1 nv read (512B) + 8 broadcast av reads (128B) feed 32
// f4-FFMAs -> 6.6x less smem-crossbar traffic than the per-anchor-warp
// scheme, zero inner-loop shuffles. Partials combined via 2KB smem buffer.
// shm: a_s4 [0,6144) floats; n_s4/psum region [6144,8320).
// ---------------------------------------------------------------------------
__device__ void tile_block(const float* __restrict__ ganch,
                           const float* __restrict__ gneg,
                           int P, int N, int aBase, int nBase, int slotBase,
                           float* shm) {
    float4* a_s4 = (float4*)shm;             // 8*192 float4
    float4* n_s4 = (float4*)(shm + 6144);    // 32*17 float4 per chunk
    float*  psum = shm + 6144;               // 8*8*32 = 2048 floats (reused)
    int tid = threadIdx.x, w = tid >> 5, lane = tid & 31;

    const float4* ga4 = (const float4*)ganch;
    for (int idx = tid; idx < 8 * 192; idx += NT) {
        int ar = idx / 192;
        int a = aBase + ar; if (a >= P) a = P - 1;
        a_s4[idx] = ga4[(size_t)a * 192 + (idx - ar * 192)];
    }

    float d0=0,d1=0,d2=0,d3=0,d4=0,d5=0,d6=0,d7=0;
    const float4* gn4 = (const float4*)gneg;
    for (int c = 0; c < 12; c++) {
        __syncthreads();
        for (int idx = tid; idx < 512; idx += NT) {
            int rrow = idx >> 4, cc = idx & 15;
            int gr = nBase + rrow; if (gr >= N) gr = N - 1;
            n_s4[rrow * 17 + cc] = gn4[(size_t)gr * 192 + c * 16 + cc];
        }
        __syncthreads();
        #pragma unroll
        for (int t = 0; t < 2; t++) {
            int kk = t * 8 + w;              // this warp's kk within chunk
            float4 nv = n_s4[lane * 17 + kk];
            int kg = c * 16 + kk;            // global f4-k index
            float4 av;
            av = a_s4[0*192+kg]; d0 += av.x*nv.x+av.y*nv.y+av.z*nv.z+av.w*nv.w;
            av = a_s4[1*192+kg]; d1 += av.x*nv.x+av.y*nv.y+av.z*nv.z+av.w*nv.w;
            av = a_s4[2*192+kg]; d2 += av.x*nv.x+av.y*nv.y+av.z*nv.z+av.w*nv.w;
            av = a_s4[3*192+kg]; d3 += av.x*nv.x+av.y*nv.y+av.z*nv.z+av.w*nv.w;
            av = a_s4[4*192+kg]; d4 += av.x*nv.x+av.y*nv.y+av.z*nv.z+av.w*nv.w;
            av = a_s4[5*192+kg]; d5 += av.x*nv.x+av.y*nv.y+av.z*nv.z+av.w*nv.w;
            av = a_s4[6*192+kg]; d6 += av.x*nv.x+av.y*nv.y+av.z*nv.z+av.w*nv.w;
            av = a_s4[7*192+kg]; d7 += av.x*nv.x+av.y*nv.y+av.z*nv.z+av.w*nv.w;
        }
    }
    __syncthreads();   // done with n_s4 chunks; reuse region as psum
    psum[0*256 + w*32 + lane] = d0;
    psum[1*256 + w*32 + lane] = d1;
    psum[2*256 + w*32 + lane] = d2;
    psum[3*256 + w*32 + lane] = d3;
    psum[4*256 + w*32 + lane] = d4;
    psum[5*256 + w*32 + lane] = d5;
    psum[6*256 + w*32 + lane] = d6;
    psum[7*256 + w*32 + lane] = d7;
    __syncthreads();
    // warp w reduces anchor aBase+w across the 8 k-partials
    {
        float sum = 0.f;
        #pragma unroll
        for (int ww = 0; ww < 8; ww++) sum += psum[w*256 + ww*32 + lane];
        int aIdx = aBase + w, jIdx = nBase + lane;
        float e = (aIdx < P && jIdx < N) ? __expf(sum * TEMP_INV) : 0.f;
        e = wsum(e);
        if (lane == 0 && aIdx < P) atomicAdd(&g_sum[slotBase + aIdx], e);
    }
}

// ---------------------------------------------------------------------------
// MLM full row (R11 loop, FROZEN — best measured) for compacted valid slot.
// ---------------------------------------------------------------------------
__device__ void mlm_row(const float* __restrict__ logits,
                        int V, int r, int lbl, int slot, float* shm) {
    int tid = threadIdx.x;
    const float* row = logits + (size_t)r * V;
    int h = (int)(((16u - ((unsigned)(size_t)row & 15u)) & 15u) >> 2);  // head floats
    if (h > V) h = V;
    int nb = (V - h) >> 2;
    int tail = V - h - (nb << 2);

    float s0 = 0.f, s1 = 0.f, s2 = 0.f, s3 = 0.f;
    if (tid < h)    s0 += __expf(row[tid]);
    if (tid < tail) s1 += __expf(row[h + (nb << 2) + tid]);

    const float4* rb = (const float4*)(row + h);
    int i = tid;
    for (; i + 7 * NT < nb; i += 8 * NT) {
        float4 v0 = __ldg(rb + i);          float4 v1 = __ldg(rb + i + NT);
        float4 v2 = __ldg(rb + i + 2 * NT); float4 v3 = __ldg(rb + i + 3 * NT);
        float4 v4 = __ldg(rb + i + 4 * NT); float4 v5 = __ldg(rb + i + 5 * NT);
        float4 v6 = __ldg(rb + i + 6 * NT); float4 v7 = __ldg(rb + i + 7 * NT);
        s0 += __expf(v0.x); s1 += __expf(v0.y); s2 += __expf(v0.z); s3 += __expf(v0.w);
        s0 += __expf(v1.x); s1 += __expf(v1.y); s2 += __expf(v1.z); s3 += __expf(v1.w);
        s0 += __expf(v2.x); s1 += __expf(v2.y); s2 += __expf(v2.z); s3 += __expf(v2.w);
        s0 += __expf(v3.x); s1 += __expf(v3.y); s2 += __expf(v3.z); s3 += __expf(v3.w);
        s0 += __expf(v4.x); s1 += __expf(v4.y); s2 += __expf(v4.z); s3 += __expf(v4.w);
        s0 += __expf(v5.x); s1 += __expf(v5.y); s2 += __expf(v5.z); s3 += __expf(v5.w);
        s0 += __expf(v6.x); s1 += __expf(v6.y); s2 += __expf(v6.z); s3 += __expf(v6.w);
        s0 += __expf(v7.x); s1 += __expf(v7.y); s2 += __expf(v7.z); s3 += __expf(v7.w);
    }
    for (; i < nb; i += NT) {
        float4 v = __ldg(rb + i);
        s0 += __expf(v.x); s1 += __expf(v.y); s2 += __expf(v.z); s3 += __expf(v.w);
    }
    float s = (s0 + s1) + (s2 + s3);
    s = wsum(s);
    if ((tid & 31) == 0) shm[tid >> 5] = s;
    __syncthreads();
    if (tid < 32) {
        float t = (tid < (NT >> 5)) ? shm[tid] : 0.f;
        t = wsum(t);
        if (tid == 0) g_nll[slot] = logf(t) - __ldg(&row[lbl]);
    }
}

// ---------------------------------------------------------------------------
// Sonnet: single block, B<=16 staged in shm (pitch 193 float4, needs shm >=
// 12416 floats — the R10 lesson).
// ---------------------------------------------------------------------------
__device__ void sonnet_block(const float* __restrict__ E, int B, int D, float* shm) {
    int tid = threadIdx.x, w = tid >> 5, lane = tid & 31;
    __shared__ float norminv[32];
    __shared__ float simbuf[32 * 32];
    __shared__ float rowloss[32];

    bool staged = (B <= 16 && D == 768);
    if (staged) {
        const float4* e4 = (const float4*)E;
        float4* s4 = (float4*)shm;   // pitch 193 float4 per row
        for (int idx = tid; idx < B * 192; idx += NT) {
            int rr = idx / 192;
            s4[rr * 193 + (idx - rr * 192)] = e4[(size_t)rr * 192 + (idx - rr * 192)];
        }
        __syncthreads();
    }
    for (int r = w; r < B; r += (NT >> 5)) {
        const float* rowp = staged ? (shm + (size_t)r * 772) : (E + (size_t)r * D);
        float ssq = 0.f;
        for (int i = lane; i < D; i += 32) { float v = rowp[i]; ssq += v * v; }
        ssq = wsum(ssq);
        if (lane == 0) norminv[r] = 1.f / fmaxf(sqrtf(ssq), 1e-12f);
    }
    __syncthreads();
    for (int t = tid; t < B * B; t += NT) {
        int i = t / B, j = t % B;
        const float* ri = staged ? (shm + (size_t)i * 772) : (E + (size_t)i * D);
        const float* rj = staged ? (shm + (size_t)j * 772) : (E + (size_t)j * D);
        float d = 0.f;
        #pragma unroll 8
        for (int k = 0; k < D; k++) d += ri[k] * rj[k];
        simbuf[i * B + j] = d * norminv[i] * norminv[j] * TEMP_INV;
    }
    __syncthreads();
    if (tid < B) {
        float m = -3e38f;
        for (int j = 0; j < B; j++) m = fmaxf(m, simbuf[tid * B + j]);
        float se = 0.f;
        for (int j = 0; j < B; j++) se += __expf(simbuf[tid * B + j] - m);
        rowloss[tid] = m + logf(se) - simbuf[tid * B + tid];
    }
    __syncthreads();
    if (tid == 0) {
        float s = 0.f;
        for (int i = 0; i < B; i++) s += rowloss[i];
        g_sonnet = s / (float)B;
    }
}

// ---------------------------------------------------------------------------
// Fused kernel: [line tiles | quat tiles | sonnet | compacted MLM slots].
// Dead slots exit before the completion protocol (expected = base + nv).
// ---------------------------------------------------------------------------
__global__ void __launch_bounds__(NT)
k_fused(const float* __restrict__ mlm_logits,
        const float* __restrict__ sonnet,
        int rows, int V,
        int Pl, int Nl, int ATl, int NTl,
        int Pq, int Nq, int ATq, int NTq,
        int Bs, int D,
        float* __restrict__ out) {
    __shared__ float shm[12416];   // sonnet staging needs full size (R10 lesson)
    __shared__ int isLast;
    int b = blockIdx.x;
    int tid = threadIdx.x;
    int TLl = ATl * NTl, TLq = ATq * NTq;
    int base = TLl + TLq + 1;
    int nv = g_nvalid;

    if (b < TLl) {
        tile_block(g_la, g_ln, Pl, Nl, (b / NTl) * 8, (b % NTl) * 32, 0, shm);
    } else if (b < TLl + TLq) {
        int bb = b - TLl;
        tile_block(g_qa, g_qn, Pq, Nq, (bb / NTq) * 8, (bb % NTq) * 32, 256, shm);
    } else if (b == TLl + TLq) {
        sonnet_block(sonnet, Bs, D, shm);
    } else {
        int slot = b - base;
        if (slot >= nv) return;   // dead slot: no protocol participation
        mlm_row(mlm_logits, V, g_vlist[slot], g_vlbl[slot], slot, shm);
    }

    // ---- completion protocol (participants = base + nv blocks) ----
    __syncthreads();
    __threadfence();
    if (tid == 0) {
        int v = atomicAdd(&g_done, 1);
        isLast = (v == base + nv - 1);
    }
    __syncthreads();
    if (!isLast) return;
    __threadfence();

    float s = 0.f, l = 0.f, q = 0.f;
    for (int i = tid; i < nv; i += NT) s += g_nll[i];
    for (int p = tid; p < Pl; p += NT) {
        float ps = g_pos[p];
        l += logf(g_sum[p] + __expf(ps)) - ps;
    }
    for (int p = tid; p < Pq; p += NT) {
        float ps = g_pos[256 + p];
        q += logf(g_sum[256 + p] + __expf(ps)) - ps;
    }
    __syncthreads();  // all reads done before re-zeroing
    for (int i = tid; i < 512; i += NT) g_sum[i] = 0.f;

    shm[tid] = s; shm[256 + tid] = l; shm[512 + tid] = q;
    __syncthreads();
    for (int off = NT >> 1; off > 0; off >>= 1) {
        if (tid < off) {
            shm[tid]       += shm[tid + off];
            shm[256 + tid] += shm[256 + tid + off];
            shm[512 + tid] += shm[512 + tid + off];
        }
        __syncthreads();
    }
    if (tid == 0) {
        float mlm = shm[0] / fmaxf((float)nv, 1.f);
        out[0] = 0.5f * mlm
               + 0.2f * shm[256] / (float)Pl
               + 0.2f * shm[512] / (float)Pq
               + 0.1f * g_sonnet;
        g_done = 0;   // reset for next graph replay
    }
}

// ---------------------------------------------------------------------------
extern "C" void kernel_launch(void* const* d_in, const int* in_sizes, int n_in,
                              void* d_out, int out_size) {
    const float* mlm_logits = (const float*)d_in[0];
    const void*  mlm_labels = d_in[1];
    const float* la = (const float*)d_in[2];
    const float* lp = (const float*)d_in[3];
    const float* ln = (const float*)d_in[4];
    const float* qa = (const float*)d_in[5];
    const float* qp = (const float*)d_in[6];
    const float* qn = (const float*)d_in[7];
    const float* so = (const float*)d_in[8];

    int rows = in_sizes[1];                        // B*S = 4096
    int V = (int)((long long)in_sizes[0] / rows);  // 30522
    const int D = 768;
    int Pl = in_sizes[2] / D, Nl = in_sizes[4] / D;
    int Pq = in_sizes[5] / D, Nq = in_sizes[7] / D;
    int Bs = in_sizes[8] / D;

    int ATl = (Pl + 7) / 8, NTl = (Nl + 31) / 32;
    int ATq = (Pq + 7) / 8, NTq = (Nq + 31) / 32;
    int tiles = ATl * NTl + ATq * NTq;
    int total = tiles + 1 + rows;

    int prepRows = Pl + Pq + Nl + Nq;
    int prepBlocks = 1 + (prepRows * 32 + NT - 1) / NT;

    k_pre<<<prepBlocks, NT>>>((const long long*)mlm_labels, rows,
                              la, lp, ln, qa, qp, qn, Pl, Pq, Nl, Nq);
    k_fused<<<total, NT>>>(mlm_logits, so,
                           rows, V, Pl, Nl, ATl, NTl, Pq, Nq, ATq, NTq,
                           Bs, D, (float*)d_out);
}